// round 2
// baseline (speedup 1.0000x reference)
#include <cuda_runtime.h>
#include <cuda_bf16.h>

#define NROWS 100000
#define SDIM  1024
#define DDIM  512
#define NRBF  8
#define FEAT  20
#define ZPAD  24   // scratch floats per row: z[20], mu, grs, g, pad

// ---- device scratch (no allocs allowed) ----
__device__ float g_scr[(size_t)NROWS * ZPAD];   // 9.6 MB, L2-resident
__device__ float g_G[FEAT * FEAT];              // W W^T / D
__device__ float g_H[FEAT];                     // W b / D
__device__ float g_Wbar[FEAT];                  // mean_d W[f,:]
__device__ float g_S[2];                        // bbar, mean(b^2)

// ============================================================
// K0: precompute LN-statistics operators (tiny)
// ============================================================
__global__ void k0_precompute(const float* __restrict__ W,
                              const float* __restrict__ b)
{
    const int tid = threadIdx.x;
    const float invD = 1.0f / DDIM;
    if (tid < FEAT * FEAT) {
        const int l = tid / FEAT, m = tid % FEAT;
        const float* wl = W + l * DDIM;
        const float* wm = W + m * DDIM;
        float s = 0.f;
        for (int d = 0; d < DDIM; d++) s = fmaf(wl[d], wm[d], s);
        g_G[tid] = s * invD;
    } else if (tid < FEAT * FEAT + FEAT) {
        const int l = tid - FEAT * FEAT;
        const float* wl = W + l * DDIM;
        float h = 0.f, wb = 0.f;
        for (int d = 0; d < DDIM; d++) { h = fmaf(wl[d], b[d], h); wb += wl[d]; }
        g_H[l] = h * invD;
        g_Wbar[l] = wb * invD;
    } else if (tid == FEAT * FEAT + FEAT) {
        float bb = 0.f, b2 = 0.f;
        for (int d = 0; d < DDIM; d++) { bb += b[d]; b2 = fmaf(b[d], b[d], b2); }
        g_S[0] = bb * invD;
        g_S[1] = b2 * invD;
    }
}

// ============================================================
// K1: warp-per-row C stats -> z, mu, grs  (reads 410MB, barrier-free)
// ============================================================
__global__ __launch_bounds__(256)
void k1_stats(const float* __restrict__ C,
              const unsigned char* __restrict__ mask,
              const float* __restrict__ gatep,
              const float* __restrict__ centers,
              const float* __restrict__ widths)
{
    const int lane = threadIdx.x & 31;
    const int wid  = threadIdx.x >> 5;
    const int gw   = (blockIdx.x * blockDim.x + threadIdx.x) >> 5;
    const int nw   = (gridDim.x * blockDim.x) >> 5;
    const float gate = *gatep;

    __shared__ float zbuf[8][FEAT];

    for (int row = gw; row < NROWS; row += nw) {
        const float4* cp = reinterpret_cast<const float4*>(C + (size_t)row * SDIM);

        // ---- 8 independent float4 loads per lane (MLP=8), clip + stats ----
        float4 v[8];
#pragma unroll
        for (int k = 0; k < 8; k++) v[k] = cp[lane + 32 * k];

        float s = 0.f, s2 = 0.f, mn = 1e30f, mx = -1e30f;
#pragma unroll
        for (int k = 0; k < 8; k++) {
            const float a0 = fminf(fmaxf(v[k].x, 0.f), 1.f);
            const float a1 = fminf(fmaxf(v[k].y, 0.f), 1.f);
            const float a2 = fminf(fmaxf(v[k].z, 0.f), 1.f);
            const float a3 = fminf(fmaxf(v[k].w, 0.f), 1.f);
            s  += (a0 + a1) + (a2 + a3);
            s2  = fmaf(a0, a0, fmaf(a1, a1, fmaf(a2, a2, fmaf(a3, a3, s2))));
            mn  = fminf(mn, fminf(fminf(a0, a1), fminf(a2, a3)));
            mx  = fmaxf(mx, fmaxf(fmaxf(a0, a1), fmaxf(a2, a3)));
        }
#pragma unroll
        for (int o = 16; o; o >>= 1) {
            s  += __shfl_xor_sync(0xffffffffu, s,  o);
            s2 += __shfl_xor_sync(0xffffffffu, s2, o);
            mn  = fminf(mn, __shfl_xor_sync(0xffffffffu, mn, o));
            mx  = fmaxf(mx, __shfl_xor_sync(0xffffffffu, mx, o));
        }
        const float mean = s  * (1.f / SDIM);
        const float m2   = s2 * (1.f / SDIM);
        const float sd   = sqrtf(fmaxf(m2 - mean * mean, 0.f));

        // ---- z[20] per lane ----
        float zl = 0.f;
        if (lane < FEAT) {
            if      (lane == 0) zl = mean;
            else if (lane == 1) zl = mx;
            else if (lane == 2) zl = mn;
            else if (lane == 3) zl = sd;
            else {
                const float v0 = (lane < 4 + NRBF) ? mean : mx;
                const int   ci = (lane < 4 + NRBF) ? (lane - 4) : (lane - 4 - NRBF);
                const float dd = (v0 - centers[ci]) / (widths[ci] + 1e-6f);
                zl = __expf(-0.5f * dd * dd);
            }
            zbuf[wid][lane] = zl;
        }
        __syncwarp();

        // ---- analytic LN stats: mu = z.wbar + bbar ; E2 = z'Gz + 2 z.h + b2 ----
        float q = 0.f, m = 0.f;
        if (lane < FEAT) {
            float gz = 0.f;
#pragma unroll
            for (int j = 0; j < FEAT; j++)
                gz = fmaf(g_G[lane * FEAT + j], zbuf[wid][j], gz);
            q = zl * fmaf(2.f, g_H[lane], gz);
            m = zl * g_Wbar[lane];
        }
#pragma unroll
        for (int o = 16; o; o >>= 1) {
            q += __shfl_xor_sync(0xffffffffu, q, o);
            m += __shfl_xor_sync(0xffffffffu, m, o);
        }
        const float mu  = m + g_S[0];
        const float E2  = q + g_S[1];
        const float var = fmaxf(E2 - mu * mu, 0.f);
        const float rs  = rsqrtf(var + 1e-5f);
        const float g   = mask[row] ? 0.f : gate;
        const float grs = g * rs;

        float* sp = g_scr + (size_t)row * ZPAD;
        if      (lane < FEAT) sp[lane] = zl;
        else if (lane == 20)  sp[20] = mu;
        else if (lane == 21)  sp[21] = grs;
        else if (lane == 22)  sp[22] = g;
    }
}

// ============================================================
// K2: elementwise matvec + LN-apply + residual  (415MB, barrier/shuffle-free)
// ============================================================
__global__ __launch_bounds__(256)
void k2_apply(const float* __restrict__ x,
              const float* __restrict__ W,
              const float* __restrict__ bias,
              const float* __restrict__ gamma,
              const float* __restrict__ beta,
              float* __restrict__ out)
{
    const int tid = threadIdx.x;
    const int d0  = tid * 2;

    float w[FEAT][2];
#pragma unroll
    for (int f = 0; f < FEAT; f++) {
        const float2 ww = *reinterpret_cast<const float2*>(W + f * DDIM + d0);
        w[f][0] = ww.x; w[f][1] = ww.y;
    }
    const float2 bb = *reinterpret_cast<const float2*>(bias  + d0);
    const float2 gg = *reinterpret_cast<const float2*>(gamma + d0);
    const float2 be = *reinterpret_cast<const float2*>(beta  + d0);

    for (int row = blockIdx.x; row < NROWS; row += gridDim.x) {
        const float4* sp = reinterpret_cast<const float4*>(g_scr + (size_t)row * ZPAD);
        float zr[24];
        *reinterpret_cast<float4*>(zr +  0) = sp[0];
        *reinterpret_cast<float4*>(zr +  4) = sp[1];
        *reinterpret_cast<float4*>(zr +  8) = sp[2];
        *reinterpret_cast<float4*>(zr + 12) = sp[3];
        *reinterpret_cast<float4*>(zr + 16) = sp[4];
        *reinterpret_cast<float4*>(zr + 20) = sp[5];
        const float2 xx = *reinterpret_cast<const float2*>(x + (size_t)row * DDIM + d0);

        float p0 = bb.x, p1 = bb.y;
#pragma unroll
        for (int f = 0; f < FEAT; f++) {
            p0 = fmaf(zr[f], w[f][0], p0);
            p1 = fmaf(zr[f], w[f][1], p1);
        }
        const float mu  = zr[20];
        const float grs = zr[21];
        const float g   = zr[22];

        const float o0 = xx.x + fmaf(grs * gg.x, p0 - mu, g * be.x);
        const float o1 = xx.y + fmaf(grs * gg.y, p1 - mu, g * be.y);
        *reinterpret_cast<float2*>(out + (size_t)row * DDIM + d0) = make_float2(o0, o1);
    }
}

extern "C" void kernel_launch(void* const* d_in, const int* in_sizes, int n_in,
                              void* d_out, int out_size)
{
    const float*         x       = (const float*)d_in[0];
    const float*         C       = (const float*)d_in[1];
    const unsigned char* mask    = (const unsigned char*)d_in[2];
    const float*         W       = (const float*)d_in[3];
    const float*         bias    = (const float*)d_in[4];
    const float*         gamma   = (const float*)d_in[5];
    const float*         beta    = (const float*)d_in[6];
    const float*         gate    = (const float*)d_in[7];
    const float*         centers = (const float*)d_in[8];
    const float*         widths  = (const float*)d_in[9];
    float*               out     = (float*)d_out;

    k0_precompute<<<1, 512>>>(W, bias);
    k1_stats<<<888, 256>>>(C, mask, gate, centers, widths);
    k2_apply<<<888, 256>>>(x, W, bias, gamma, beta, out);
}

// round 4
// speedup vs baseline: 3.0717x; 3.0717x over previous
#include <cuda_runtime.h>
#include <cuda_bf16.h>

#define NROWS 100000
#define SDIM  1024
#define DDIM  512
#define NRBF  8
#define FEAT  20
#define GPITCH 21           // padded G row (odd => conflict-free LDS)

// ---- device scratch for LN-statistics operators ----
__device__ float g_G[FEAT * FEAT];   // W W^T / D
__device__ float g_H[FEAT];          // W b / D
__device__ float g_Wbar[FEAT];       // mean_d W[f,:]
__device__ float g_S[2];             // mean(b), mean(b^2)

// ============================================================
// K0: warp-per-item precompute (421 items), ~3us
// ============================================================
__global__ void k0_precompute(const float* __restrict__ W,
                              const float* __restrict__ b)
{
    const int lane = threadIdx.x & 31;
    const int item = (blockIdx.x * blockDim.x + threadIdx.x) >> 5;
    const float invD = 1.0f / DDIM;

    if (item < FEAT * FEAT) {
        const int l = item / FEAT, m = item % FEAT;
        const float4* wl = reinterpret_cast<const float4*>(W + l * DDIM);
        const float4* wm = reinterpret_cast<const float4*>(W + m * DDIM);
        float s = 0.f;
#pragma unroll
        for (int k = 0; k < 4; k++) {
            const float4 a = wl[lane + 32 * k];
            const float4 c = wm[lane + 32 * k];
            s = fmaf(a.x, c.x, fmaf(a.y, c.y, fmaf(a.z, c.z, fmaf(a.w, c.w, s))));
        }
#pragma unroll
        for (int o = 16; o; o >>= 1) s += __shfl_xor_sync(0xffffffffu, s, o);
        if (lane == 0) g_G[item] = s * invD;
    } else if (item < FEAT * FEAT + FEAT) {
        const int l = item - FEAT * FEAT;
        const float4* wl = reinterpret_cast<const float4*>(W + l * DDIM);
        const float4* bp = reinterpret_cast<const float4*>(b);
        float h = 0.f, wb = 0.f;
#pragma unroll
        for (int k = 0; k < 4; k++) {
            const float4 a = wl[lane + 32 * k];
            const float4 c = bp[lane + 32 * k];
            h  = fmaf(a.x, c.x, fmaf(a.y, c.y, fmaf(a.z, c.z, fmaf(a.w, c.w, h))));
            wb += (a.x + a.y) + (a.z + a.w);
        }
#pragma unroll
        for (int o = 16; o; o >>= 1) {
            h  += __shfl_xor_sync(0xffffffffu, h,  o);
            wb += __shfl_xor_sync(0xffffffffu, wb, o);
        }
        if (lane == 0) { g_H[l] = h * invD; g_Wbar[l] = wb * invD; }
    } else if (item == FEAT * FEAT + FEAT) {
        const float4* bp = reinterpret_cast<const float4*>(b);
        float bb = 0.f, b2 = 0.f;
#pragma unroll
        for (int k = 0; k < 4; k++) {
            const float4 c = bp[lane + 32 * k];
            bb += (c.x + c.y) + (c.z + c.w);
            b2  = fmaf(c.x, c.x, fmaf(c.y, c.y, fmaf(c.z, c.z, fmaf(c.w, c.w, b2))));
        }
#pragma unroll
        for (int o = 16; o; o >>= 1) {
            bb += __shfl_xor_sync(0xffffffffu, bb, o);
            b2 += __shfl_xor_sync(0xffffffffu, b2, o);
        }
        if (lane == 0) { g_S[0] = bb * invD; g_S[1] = b2 * invD; }
    }
}

// ============================================================
// Fused: 8 rows per block-iteration, 2 barriers / 8 rows
// ============================================================
__global__ __launch_bounds__(256)
void fused_kernel(const float* __restrict__ x,
                  const float* __restrict__ C,
                  const unsigned char* __restrict__ mask,
                  const float* __restrict__ W,
                  const float* __restrict__ bias,
                  const float* __restrict__ gamma,
                  const float* __restrict__ beta,
                  const float* __restrict__ gatep,
                  const float* __restrict__ centers,
                  const float* __restrict__ widths,
                  float* __restrict__ out)
{
    const int tid  = threadIdx.x;
    const int lane = tid & 31;
    const int wid  = tid >> 5;
    const int d0   = tid * 2;
    const float gate = *gatep;

    __shared__ float sG[FEAT * GPITCH]; // padded Gram
    __shared__ float sH[FEAT], sWb[FEAT], sS[2];
    __shared__ float sCW[2 * NRBF];
    __shared__ float zmu[8][24];        // per-row: z[20], mu, grs, g, pad

    // FIX (R3 bug): 400 Gram entries copied by 256 threads -> must loop
    for (int i = tid; i < FEAT * FEAT; i += 256)
        sG[(i / FEAT) * GPITCH + (i % FEAT)] = g_G[i];
    if (tid < FEAT)  { sH[tid] = g_H[tid]; sWb[tid] = g_Wbar[tid]; }
    if (tid < 2)       sS[tid] = g_S[tid];
    if (tid < NRBF)  { sCW[tid] = centers[tid]; sCW[NRBF + tid] = widths[tid]; }
    if (tid < 8)       zmu[tid][23] = 0.f;    // pad lane read by float4

    // register-resident weight slice
    float w[FEAT][2];
#pragma unroll
    for (int f = 0; f < FEAT; f++) {
        const float2 ww = *reinterpret_cast<const float2*>(W + f * DDIM + d0);
        w[f][0] = ww.x; w[f][1] = ww.y;
    }
    const float2 bb = *reinterpret_cast<const float2*>(bias  + d0);
    const float2 gg = *reinterpret_cast<const float2*>(gamma + d0);
    const float2 be = *reinterpret_cast<const float2*>(beta  + d0);
    __syncthreads();

    for (int base = blockIdx.x * 8; base < NROWS; base += gridDim.x * 8) {
        const int myrow = base + wid;   // NROWS % 8 == 0, always valid

        // ---- prefetch x for all 8 rows (independent of C stream) ----
        float2 x2[8];
#pragma unroll
        for (int r = 0; r < 8; r++)
            x2[r] = *reinterpret_cast<const float2*>(x + (size_t)(base + r) * DDIM + d0);

        // ---- phase 1: warp-per-row C stats ----
        const float4* cp = reinterpret_cast<const float4*>(C + (size_t)myrow * SDIM);
        float s = 0.f, s2 = 0.f, mn = 1e30f, mx = -1e30f;
#pragma unroll
        for (int h = 0; h < 2; h++) {
            float4 v[4];
#pragma unroll
            for (int k = 0; k < 4; k++) v[k] = cp[lane + 32 * (4 * h + k)];
#pragma unroll
            for (int k = 0; k < 4; k++) {
                const float a0 = fminf(fmaxf(v[k].x, 0.f), 1.f);
                const float a1 = fminf(fmaxf(v[k].y, 0.f), 1.f);
                const float a2 = fminf(fmaxf(v[k].z, 0.f), 1.f);
                const float a3 = fminf(fmaxf(v[k].w, 0.f), 1.f);
                s  += (a0 + a1) + (a2 + a3);
                s2  = fmaf(a0, a0, fmaf(a1, a1, fmaf(a2, a2, fmaf(a3, a3, s2))));
                mn  = fminf(mn, fminf(fminf(a0, a1), fminf(a2, a3)));
                mx  = fmaxf(mx, fmaxf(fmaxf(a0, a1), fmaxf(a2, a3)));
            }
        }
#pragma unroll
        for (int o = 16; o; o >>= 1) {
            s  += __shfl_xor_sync(0xffffffffu, s,  o);
            s2 += __shfl_xor_sync(0xffffffffu, s2, o);
            mn  = fminf(mn, __shfl_xor_sync(0xffffffffu, mn, o));
            mx  = fmaxf(mx, __shfl_xor_sync(0xffffffffu, mx, o));
        }
        const float mean = s  * (1.f / SDIM);
        const float m2   = s2 * (1.f / SDIM);
        const float sd   = sqrtf(fmaxf(m2 - mean * mean, 0.f));

        // ---- z per lane (lanes 0..19) ----
        float zl = 0.f;
        if (lane < FEAT) {
            if      (lane == 0) zl = mean;
            else if (lane == 1) zl = mx;
            else if (lane == 2) zl = mn;
            else if (lane == 3) zl = sd;
            else {
                const float v0 = (lane < 4 + NRBF) ? mean : mx;
                const int   ci = (lane < 4 + NRBF) ? (lane - 4) : (lane - 4 - NRBF);
                const float dd = (v0 - sCW[ci]) / (sCW[NRBF + ci] + 1e-6f);
                zl = __expf(-0.5f * dd * dd);
            }
            zmu[wid][lane] = zl;
        }
        __syncwarp();

        // ---- analytic LN stats: mu = z.wbar + bbar ; E2 = z'Gz + 2 z.h + b2 ----
        float q = 0.f, m = 0.f;
        if (lane < FEAT) {
            float gz = 0.f;
#pragma unroll
            for (int j = 0; j < FEAT; j++)
                gz = fmaf(sG[lane * GPITCH + j], zmu[wid][j], gz);
            q = zl * fmaf(2.f, sH[lane], gz);
            m = zl * sWb[lane];
        }
#pragma unroll
        for (int o = 16; o; o >>= 1) {
            q += __shfl_xor_sync(0xffffffffu, q, o);
            m += __shfl_xor_sync(0xffffffffu, m, o);
        }
        if (lane == 0) {
            const float mu  = m + sS[0];
            const float var = fmaxf(q + sS[1] - mu * mu, 0.f);
            const float g   = mask[myrow] ? 0.f : gate;
            zmu[wid][20] = mu;
            zmu[wid][21] = g * rsqrtf(var + 1e-5f);
            zmu[wid][22] = g;
        }
        __syncthreads();   // A: all 8 rows' z/mu ready

        // ---- phase 2: apply for 8 rows, each thread owns 2 dims ----
#pragma unroll
        for (int r = 0; r < 8; r++) {
            float zr[24];
            const float4* sp = reinterpret_cast<const float4*>(zmu[r]);
#pragma unroll
            for (int k = 0; k < 6; k++) *reinterpret_cast<float4*>(zr + 4 * k) = sp[k];

            float p0 = bb.x, p1 = bb.y;
#pragma unroll
            for (int f = 0; f < FEAT; f++) {
                p0 = fmaf(zr[f], w[f][0], p0);
                p1 = fmaf(zr[f], w[f][1], p1);
            }
            const float mu = zr[20], grs = zr[21], g = zr[22];
            const float o0 = fmaf(grs * gg.x, p0 - mu, fmaf(g, be.x, x2[r].x));
            const float o1 = fmaf(grs * gg.y, p1 - mu, fmaf(g, be.y, x2[r].y));
            *reinterpret_cast<float2*>(out + (size_t)(base + r) * DDIM + d0) =
                make_float2(o0, o1);
        }
        __syncthreads();   // B: protect zmu for next iteration
    }
}

extern "C" void kernel_launch(void* const* d_in, const int* in_sizes, int n_in,
                              void* d_out, int out_size)
{
    const float*         x       = (const float*)d_in[0];
    const float*         C       = (const float*)d_in[1];
    const unsigned char* mask    = (const unsigned char*)d_in[2];
    const float*         W       = (const float*)d_in[3];
    const float*         bias    = (const float*)d_in[4];
    const float*         gamma   = (const float*)d_in[5];
    const float*         beta    = (const float*)d_in[6];
    const float*         gate    = (const float*)d_in[7];
    const float*         centers = (const float*)d_in[8];
    const float*         widths  = (const float*)d_in[9];
    float*               out     = (float*)d_out;

    k0_precompute<<<53, 256>>>(W, bias);   // 424 warps >= 421 items
    fused_kernel<<<296, 256>>>(x, C, mask, W, bias, gamma, beta,
                               gate, centers, widths, out);
}

// round 5
// speedup vs baseline: 3.1997x; 1.0417x over previous
#include <cuda_runtime.h>
#include <cuda_bf16.h>

#define NROWS 100000
#define SDIM  1024
#define DDIM  512
#define NRBF  8
#define FEAT  20
#define GPITCH 21

// dynamic smem layout (floats): C double buf 2*8192, x double buf 2*4096
#define SM_C_FLOATS 8192
#define SM_X_FLOATS 4096
#define DSMEM_BYTES ((2 * SM_C_FLOATS + 2 * SM_X_FLOATS) * 4)   // 98304

__device__ float g_G[FEAT * FEAT];
__device__ float g_H[FEAT];
__device__ float g_Wbar[FEAT];
__device__ float g_S[2];

__device__ __forceinline__ void cp16(void* dst, const void* src) {
    unsigned d = (unsigned)__cvta_generic_to_shared(dst);
    asm volatile("cp.async.cg.shared.global [%0], [%1], 16;" :: "r"(d), "l"(src));
}

// ============================================================
// K0: warp-per-item precompute (421 items)
// ============================================================
__global__ void k0_precompute(const float* __restrict__ W,
                              const float* __restrict__ b)
{
    const int lane = threadIdx.x & 31;
    const int item = (blockIdx.x * blockDim.x + threadIdx.x) >> 5;
    const float invD = 1.0f / DDIM;

    if (item < FEAT * FEAT) {
        const int l = item / FEAT, m = item % FEAT;
        const float4* wl = reinterpret_cast<const float4*>(W + l * DDIM);
        const float4* wm = reinterpret_cast<const float4*>(W + m * DDIM);
        float s = 0.f;
#pragma unroll
        for (int k = 0; k < 4; k++) {
            const float4 a = wl[lane + 32 * k];
            const float4 c = wm[lane + 32 * k];
            s = fmaf(a.x, c.x, fmaf(a.y, c.y, fmaf(a.z, c.z, fmaf(a.w, c.w, s))));
        }
#pragma unroll
        for (int o = 16; o; o >>= 1) s += __shfl_xor_sync(0xffffffffu, s, o);
        if (lane == 0) g_G[item] = s * invD;
    } else if (item < FEAT * FEAT + FEAT) {
        const int l = item - FEAT * FEAT;
        const float4* wl = reinterpret_cast<const float4*>(W + l * DDIM);
        const float4* bp = reinterpret_cast<const float4*>(b);
        float h = 0.f, wb = 0.f;
#pragma unroll
        for (int k = 0; k < 4; k++) {
            const float4 a = wl[lane + 32 * k];
            const float4 c = bp[lane + 32 * k];
            h  = fmaf(a.x, c.x, fmaf(a.y, c.y, fmaf(a.z, c.z, fmaf(a.w, c.w, h))));
            wb += (a.x + a.y) + (a.z + a.w);
        }
#pragma unroll
        for (int o = 16; o; o >>= 1) {
            h  += __shfl_xor_sync(0xffffffffu, h,  o);
            wb += __shfl_xor_sync(0xffffffffu, wb, o);
        }
        if (lane == 0) { g_H[l] = h * invD; g_Wbar[l] = wb * invD; }
    } else if (item == FEAT * FEAT + FEAT) {
        const float4* bp = reinterpret_cast<const float4*>(b);
        float bb = 0.f, b2 = 0.f;
#pragma unroll
        for (int k = 0; k < 4; k++) {
            const float4 c = bp[lane + 32 * k];
            bb += (c.x + c.y) + (c.z + c.w);
            b2  = fmaf(c.x, c.x, fmaf(c.y, c.y, fmaf(c.z, c.z, fmaf(c.w, c.w, b2))));
        }
#pragma unroll
        for (int o = 16; o; o >>= 1) {
            bb += __shfl_xor_sync(0xffffffffu, bb, o);
            b2 += __shfl_xor_sync(0xffffffffu, b2, o);
        }
        if (lane == 0) { g_S[0] = bb * invD; g_S[1] = b2 * invD; }
    }
}

// ============================================================
// Fused, cp.async double-buffered: 8 rows / iteration
// ============================================================
__global__ __launch_bounds__(256)
void fused_kernel(const float* __restrict__ x,
                  const float* __restrict__ C,
                  const unsigned char* __restrict__ mask,
                  const float* __restrict__ W,
                  const float* __restrict__ bias,
                  const float* __restrict__ gamma,
                  const float* __restrict__ beta,
                  const float* __restrict__ gatep,
                  const float* __restrict__ centers,
                  const float* __restrict__ widths,
                  float* __restrict__ out)
{
    extern __shared__ float dsm[];
    float* sC = dsm;                          // [2][8192]
    float* sX = dsm + 2 * SM_C_FLOATS;        // [2][4096]

    const int tid  = threadIdx.x;
    const int lane = tid & 31;
    const int wid  = tid >> 5;
    const int d0   = tid * 2;
    const float gate = *gatep;

    __shared__ float sG[FEAT * GPITCH];
    __shared__ float sH[FEAT], sWb[FEAT], sS[2];
    __shared__ float sCW[2 * NRBF];
    __shared__ float zmu[8][24];

    for (int i = tid; i < FEAT * FEAT; i += 256)
        sG[(i / FEAT) * GPITCH + (i % FEAT)] = g_G[i];
    if (tid < FEAT)  { sH[tid] = g_H[tid]; sWb[tid] = g_Wbar[tid]; }
    if (tid < 2)       sS[tid] = g_S[tid];
    if (tid < NRBF)  { sCW[tid] = centers[tid]; sCW[NRBF + tid] = widths[tid]; }
    if (tid < 8)       zmu[tid][23] = 0.f;

    float w[FEAT][2];
#pragma unroll
    for (int f = 0; f < FEAT; f++) {
        const float2 ww = *reinterpret_cast<const float2*>(W + f * DDIM + d0);
        w[f][0] = ww.x; w[f][1] = ww.y;
    }
    const float2 bb = *reinterpret_cast<const float2*>(bias  + d0);
    const float2 gg = *reinterpret_cast<const float2*>(gamma + d0);
    const float2 be = *reinterpret_cast<const float2*>(beta  + d0);

    const int step = gridDim.x * 8;
    int base = blockIdx.x * 8;

    // ---- prologue: async-copy tile 0 (gmem tile is contiguous) ----
    if (base < NROWS) {
        const float* gC = C + (size_t)base * SDIM;
        const float* gx = x + (size_t)base * DDIM;
#pragma unroll
        for (int k = 0; k < 8; k++) cp16(sC + (tid + 256 * k) * 4, gC + (tid + 256 * k) * 4);
#pragma unroll
        for (int k = 0; k < 4; k++) cp16(sX + (tid + 256 * k) * 4, gx + (tid + 256 * k) * 4);
        asm volatile("cp.async.commit_group;" ::: "memory");
    }

    int buf = 0;
    for (; base < NROWS; base += step, buf ^= 1) {
        const int nb = base + step;
        const bool havenext = nb < NROWS;
        if (havenext) {
            float* dC = sC + (buf ^ 1) * SM_C_FLOATS;
            float* dX = sX + (buf ^ 1) * SM_X_FLOATS;
            const float* gC = C + (size_t)nb * SDIM;
            const float* gx = x + (size_t)nb * DDIM;
#pragma unroll
            for (int k = 0; k < 8; k++) cp16(dC + (tid + 256 * k) * 4, gC + (tid + 256 * k) * 4);
#pragma unroll
            for (int k = 0; k < 4; k++) cp16(dX + (tid + 256 * k) * 4, gx + (tid + 256 * k) * 4);
            asm volatile("cp.async.commit_group;" ::: "memory");
            asm volatile("cp.async.wait_group 1;" ::: "memory");
        } else {
            asm volatile("cp.async.wait_group 0;" ::: "memory");
        }
        __syncthreads();   // tile[buf] resident for all warps

        const int myrow = base + wid;

        // ---- phase 1: warp-per-row stats from smem ----
        const float4* cp4 = reinterpret_cast<const float4*>(sC + buf * SM_C_FLOATS + wid * SDIM);
        float s = 0.f, s2 = 0.f, mn = 1e30f, mx = -1e30f;
#pragma unroll
        for (int h = 0; h < 2; h++) {
            float4 v[4];
#pragma unroll
            for (int k = 0; k < 4; k++) v[k] = cp4[lane + 32 * (4 * h + k)];
#pragma unroll
            for (int k = 0; k < 4; k++) {
                const float a0 = fminf(fmaxf(v[k].x, 0.f), 1.f);
                const float a1 = fminf(fmaxf(v[k].y, 0.f), 1.f);
                const float a2 = fminf(fmaxf(v[k].z, 0.f), 1.f);
                const float a3 = fminf(fmaxf(v[k].w, 0.f), 1.f);
                s  += (a0 + a1) + (a2 + a3);
                s2  = fmaf(a0, a0, fmaf(a1, a1, fmaf(a2, a2, fmaf(a3, a3, s2))));
                mn  = fminf(mn, fminf(fminf(a0, a1), fminf(a2, a3)));
                mx  = fmaxf(mx, fmaxf(fmaxf(a0, a1), fmaxf(a2, a3)));
            }
        }
#pragma unroll
        for (int o = 16; o; o >>= 1) {
            s  += __shfl_xor_sync(0xffffffffu, s,  o);
            s2 += __shfl_xor_sync(0xffffffffu, s2, o);
            mn  = fminf(mn, __shfl_xor_sync(0xffffffffu, mn, o));
            mx  = fmaxf(mx, __shfl_xor_sync(0xffffffffu, mx, o));
        }
        const float mean = s  * (1.f / SDIM);
        const float m2   = s2 * (1.f / SDIM);
        const float sd   = sqrtf(fmaxf(m2 - mean * mean, 0.f));

        float zl = 0.f;
        if (lane < FEAT) {
            if      (lane == 0) zl = mean;
            else if (lane == 1) zl = mx;
            else if (lane == 2) zl = mn;
            else if (lane == 3) zl = sd;
            else {
                const float v0 = (lane < 4 + NRBF) ? mean : mx;
                const int   ci = (lane < 4 + NRBF) ? (lane - 4) : (lane - 4 - NRBF);
                const float dd = (v0 - sCW[ci]) / (sCW[NRBF + ci] + 1e-6f);
                zl = __expf(-0.5f * dd * dd);
            }
            zmu[wid][lane] = zl;
        }
        __syncwarp();

        // ---- analytic LN: mu = z.wbar + bbar ; E2 = z'Gz + 2 z.h + mean(b^2) ----
        float q = 0.f, m = 0.f;
        if (lane < FEAT) {
            float gz = 0.f;
#pragma unroll
            for (int j = 0; j < FEAT; j++)
                gz = fmaf(sG[lane * GPITCH + j], zmu[wid][j], gz);
            q = zl * fmaf(2.f, sH[lane], gz);
            m = zl * sWb[lane];
        }
#pragma unroll
        for (int o = 16; o; o >>= 1) {
            q += __shfl_xor_sync(0xffffffffu, q, o);
            m += __shfl_xor_sync(0xffffffffu, m, o);
        }
        if (lane == 0) {
            const float mu  = m + sS[0];
            const float var = fmaxf(q + sS[1] - mu * mu, 0.f);
            const float g   = mask[myrow] ? 0.f : gate;
            zmu[wid][20] = mu;
            zmu[wid][21] = g * rsqrtf(var + 1e-5f);
            zmu[wid][22] = g;
        }
        __syncthreads();   // A

        // ---- phase 2: apply 8 rows ----
        const float* xb = sX + buf * SM_X_FLOATS;
#pragma unroll
        for (int r = 0; r < 8; r++) {
            float zr[24];
            const float4* sp = reinterpret_cast<const float4*>(zmu[r]);
#pragma unroll
            for (int k = 0; k < 6; k++) *reinterpret_cast<float4*>(zr + 4 * k) = sp[k];
            const float2 xx = *reinterpret_cast<const float2*>(xb + r * DDIM + d0);

            float p0 = bb.x, p1 = bb.y;
#pragma unroll
            for (int f = 0; f < FEAT; f++) {
                p0 = fmaf(zr[f], w[f][0], p0);
                p1 = fmaf(zr[f], w[f][1], p1);
            }
            const float mu = zr[20], grs = zr[21], g = zr[22];
            const float o0 = fmaf(grs * gg.x, p0 - mu, fmaf(g, be.x, xx.x));
            const float o1 = fmaf(grs * gg.y, p1 - mu, fmaf(g, be.y, xx.y));
            *reinterpret_cast<float2*>(out + (size_t)(base + r) * DDIM + d0) =
                make_float2(o0, o1);
        }
        __syncthreads();   // B: done reading buf before it is overwritten
    }
}

extern "C" void kernel_launch(void* const* d_in, const int* in_sizes, int n_in,
                              void* d_out, int out_size)
{
    const float*         x       = (const float*)d_in[0];
    const float*         C       = (const float*)d_in[1];
    const unsigned char* mask    = (const unsigned char*)d_in[2];
    const float*         W       = (const float*)d_in[3];
    const float*         bias    = (const float*)d_in[4];
    const float*         gamma   = (const float*)d_in[5];
    const float*         beta    = (const float*)d_in[6];
    const float*         gate    = (const float*)d_in[7];
    const float*         centers = (const float*)d_in[8];
    const float*         widths  = (const float*)d_in[9];
    float*               out     = (float*)d_out;

    static bool attr_set = false;
    if (!attr_set) {
        cudaFuncSetAttribute(fused_kernel,
                             cudaFuncAttributeMaxDynamicSharedMemorySize, DSMEM_BYTES);
        attr_set = true;
    }

    k0_precompute<<<53, 256>>>(W, bias);
    fused_kernel<<<296, 256, DSMEM_BYTES>>>(x, C, mask, W, bias, gamma, beta,
                                            gate, centers, widths, out);
}